// round 14
// baseline (speedup 1.0000x reference)
#include <cuda_runtime.h>
#include <cuda_fp16.h>
#include <cstdint>

#define NEG_INF_F (-1000000000.0f)

// ---------------- scratch (halves) ----------------
__device__ __half g_low16[37748736];
__device__ __half g_hf16 [37748736];
__device__ __half g_qf16 [18874368];
__device__ __half g_vf16 [18874368];
__device__ __half g_vf216[18874368];
__device__ __half g_qb16 [2359296];
__device__ __half g_kb16 [2359296];
__device__ __half g_qt16 [2359296];
__device__ __half g_kt16 [2359296];
__device__ __half g_vb16 [18874368];
__device__ __half g_vt16 [18874368];
__device__ __half g_attH16[7077888];
__device__ __half g_attW16[7077888];
__device__ __half g_oh16 [18874368];
__device__ __half g_ow16 [18874368];
__device__ __half g_w16  [737280];
__device__ float  g_stats[1024];

#define W_C1 0
#define W_C2 131072
#define W_V  262144
#define W_K  327680
#define W_Q  335872
#define W_BW 344064

__global__ void wcvt_kernel(const float* c1, const float* c2, const float* vw,
                            const float* kw, const float* qw, const float* bw,
                            __half* w16) {
    for (int i = blockIdx.x * blockDim.x + threadIdx.x; i < 737280;
         i += gridDim.x * blockDim.x) {
        float v;
        if (i < W_C2) v = c1[i];
        else if (i < W_V) v = c2[i - W_C2];
        else if (i < W_K) v = vw[i - W_V];
        else if (i < W_Q) v = kw[i - W_K];
        else if (i < W_BW) v = qw[i - W_Q];
        else v = bw[i - W_BW];
        w16[i] = __float2half_rn(v);
    }
}

// resize high->hf16 (bilinear 2x), convert low->low16, zero stats
__global__ void resize_kernel(const float* __restrict__ in, __half* __restrict__ out,
                              const float* __restrict__ low, __half* __restrict__ low16,
                              float* __restrict__ stats) {
    long gtid = (long)blockIdx.x * blockDim.x + threadIdx.x;
    if (gtid < 1024) stats[gtid] = 0.0f;
    long total4 = 8L * 512 * 96 * 24;
    for (long idx = gtid; idx < total4; idx += (long)gridDim.x * blockDim.x) {
        int ox0 = (int)(idx % 24) * 4;
        long t  = idx / 24;
        int oy = (int)(t % 96);
        long bc = t / 96;
        int my = oy >> 1;
        int y0, y1; float wy0;
        if (oy & 1) { y0 = my; y1 = (my < 47) ? my + 1 : 47; wy0 = 0.75f; }
        else        { y0 = (my > 0) ? my - 1 : 0; y1 = my;   wy0 = 0.25f; }
        const float* p = in + bc * 2304;
        float r[4];
        #pragma unroll
        for (int j = 0; j < 4; j++) {
            int ox = ox0 + j, mx = ox >> 1;
            int x0, x1; float wx0;
            if (ox & 1) { x0 = mx; x1 = (mx < 47) ? mx + 1 : 47; wx0 = 0.75f; }
            else        { x0 = (mx > 0) ? mx - 1 : 0; x1 = mx;   wx0 = 0.25f; }
            float top = wx0 * p[y0*48+x0] + (1.f-wx0) * p[y0*48+x1];
            float bot = wx0 * p[y1*48+x0] + (1.f-wx0) * p[y1*48+x1];
            r[j] = wy0 * top + (1.f-wy0) * bot;
        }
        __half2 h01 = __floats2half2_rn(r[0], r[1]);
        __half2 h23 = __floats2half2_rn(r[2], r[3]);
        uint2 pk; pk.x = *(uint32_t*)&h01; pk.y = *(uint32_t*)&h23;
        *(uint2*)(out + idx * 4) = pk;
    }
    long totalL = 37748736L / 4;
    for (long idx = gtid; idx < totalL; idx += (long)gridDim.x * blockDim.x) {
        float4 v = *(const float4*)(low + idx * 4);
        __half2 h01 = __floats2half2_rn(v.x, v.y);
        __half2 h23 = __floats2half2_rn(v.z, v.w);
        uint2 pk; pk.x = *(uint32_t*)&h01; pk.y = *(uint32_t*)&h23;
        *(uint2*)(low16 + idx * 4) = pk;
    }
}

__device__ __forceinline__ void cp16(uint32_t dst, const void* src) {
    asm volatile("cp.async.cg.shared.global [%0], [%1], 16;"
                 :: "r"(dst), "l"(src));
}
__device__ __forceinline__ void mma_f16(float* c, const uint32_t* a, uint32_t b0, uint32_t b1) {
    asm volatile("mma.sync.aligned.m16n8k16.row.col.f32.f16.f16.f32 "
                 "{%0,%1,%2,%3}, {%4,%5,%6,%7}, {%8,%9}, {%0,%1,%2,%3};"
                 : "+f"(c[0]), "+f"(c[1]), "+f"(c[2]), "+f"(c[3])
                 : "r"(a[0]), "r"(a[1]), "r"(a[2]), "r"(a[3]), "r"(b0), "r"(b1));
}
#define LDSM_X4(r0, r1, r2, r3, addr) \
    asm volatile("ldmatrix.sync.aligned.m8n8.x4.shared.b16 {%0,%1,%2,%3}, [%4];" \
                 : "=r"(r0), "=r"(r1), "=r"(r2), "=r"(r3) : "r"(addr))
#define LDSM_X4_T(r0, r1, r2, r3, addr) \
    asm volatile("ldmatrix.sync.aligned.m8n8.x4.trans.shared.b16 {%0,%1,%2,%3}, [%4];" \
                 : "=r"(r0), "=r"(r1), "=r"(r2), "=r"(r3) : "r"(addr))

#define HAP 40
#define HBP 264      // hgemm32 (N-tile 256)
#define HBP2 136     // hgemm   (N-tile 128)

// ======= fp16 GEMM: block 128x128x32, warp 64x32, 4-stage, 2 CTAs/SM =======
#define HA_STG (128*HAP)
#define HB2_STG (32*HBP2)
#define GEMMH_SMEM (4*(HA_STG+HB2_STG)*2)

__global__ void __launch_bounds__(256, 2) hgemm_kernel(
    const __half* __restrict__ A, int lda,
    const __half* __restrict__ B1, long long b1s,
    const __half* __restrict__ B2, long long b2s, int kSplit,
    const float* __restrict__ bias,
    __half* __restrict__ Cm, long long cStride,
    int K, int N, float* __restrict__ stats)
{
    extern __shared__ __half smh[];
    __half* sA = smh;
    __half* sB = smh + 4 * HA_STG;
    const uint32_t sA_u = (uint32_t)__cvta_generic_to_shared(sA);
    const uint32_t sB_u = (uint32_t)__cvta_generic_to_shared(sB);
    __shared__ float bnS[128], bnQ[128];

    const int tid = threadIdx.x;
    if (tid < 128) { bnS[tid] = 0.0f; bnQ[tid] = 0.0f; }
    const int warp = tid >> 5, lane = tid & 31;
    const int g = lane >> 2, tq = lane & 3;
    const int wm = (warp >> 2) * 64;
    const int wn = (warp & 3) * 32;
    const int m0 = blockIdx.y * 128;
    const int n0 = blockIdx.x * 128;
    const __half* B1b = B1 + (long long)blockIdx.z * b1s;
    const __half* B2b = B2 ? (B2 + (long long)blockIdx.z * b2s) : B1b;
    const bool split = (B2 != nullptr);

    int arow[2], acol[2];
    const __half* aSrc[2];
    #pragma unroll
    for (int i = 0; i < 2; i++) {
        int ch = tid + 256 * i;
        arow[i] = ch >> 2;  acol[i] = (ch & 3) * 8;
        aSrc[i] = A + (long long)(m0 + arow[i]) * lda + acol[i];
    }
    int brow[2], bnoff[2], bdst[2];
    const __half* bSrcBase[2];
    #pragma unroll
    for (int i = 0; i < 2; i++) {
        int ch = tid + 256 * i;
        brow[i] = ch >> 4;
        int c8 = ch & 15;
        bnoff[i] = n0 + c8 * 8;
        bdst[i] = (brow[i] * HBP2 + c8 * 8) * 2;
        bSrcBase[i] = B1b + (long long)brow[i] * N + bnoff[i];
    }
    const int lsub = lane >> 3, lr = lane & 7;
    const int kl = (lsub & 1) * 8 + lr;
    const int nl = (lsub >> 1) * 8;
    uint32_t bmOff[2];
    #pragma unroll
    for (int p = 0; p < 2; p++)
        bmOff[p] = (uint32_t)((kl * HBP2 + wn + p * 16 + nl) * 2);
    const uint32_t aOff = (uint32_t)((kl * HAP + nl) * 2);

    const int nch = K >> 5;

    #pragma unroll
    for (int c = 0; c < 3; c++) {
        int kc = c * 32;
        uint32_t da = sA_u + (c * HA_STG) * 2;
        uint32_t db = sB_u + (c * HB2_STG) * 2;
        #pragma unroll
        for (int i = 0; i < 2; i++)
            cp16(da + (arow[i] * HAP + acol[i]) * 2, aSrc[i] + kc);
        if (split) {
            #pragma unroll
            for (int i = 0; i < 2; i++) {
                int row = kc + brow[i];
                const __half* src = (row < kSplit) ? (B1b + (long long)row * N + bnoff[i])
                                                   : (B2b + (long long)(row - kSplit) * N + bnoff[i]);
                cp16(db + bdst[i], src);
            }
        } else {
            #pragma unroll
            for (int i = 0; i < 2; i++)
                cp16(db + bdst[i], bSrcBase[i] + (long long)kc * N);
        }
        asm volatile("cp.async.commit_group;");
    }

    float acc[4][4][4];
    #pragma unroll
    for (int mf = 0; mf < 4; mf++)
        #pragma unroll
        for (int nf = 0; nf < 4; nf++)
            #pragma unroll
            for (int i = 0; i < 4; i++) acc[mf][nf][i] = 0.0f;

    for (int c = 0; c < nch; c++) {
        if (c + 3 <= nch)      asm volatile("cp.async.wait_group 2;");
        else if (c + 2 == nch) asm volatile("cp.async.wait_group 1;");
        else                   asm volatile("cp.async.wait_group 0;");
        __syncthreads();

        if (c + 3 < nch) {
            int s = (c + 3) & 3;
            int kc = (c + 3) * 32;
            uint32_t da = sA_u + (s * HA_STG) * 2;
            uint32_t db = sB_u + (s * HB2_STG) * 2;
            #pragma unroll
            for (int i = 0; i < 2; i++)
                cp16(da + (arow[i] * HAP + acol[i]) * 2, aSrc[i] + kc);
            if (split) {
                #pragma unroll
                for (int i = 0; i < 2; i++) {
                    int row = kc + brow[i];
                    const __half* src = (row < kSplit) ? (B1b + (long long)row * N + bnoff[i])
                                                       : (B2b + (long long)(row - kSplit) * N + bnoff[i]);
                    cp16(db + bdst[i], src);
                }
            } else {
                #pragma unroll
                for (int i = 0; i < 2; i++)
                    cp16(db + bdst[i], bSrcBase[i] + (long long)kc * N);
            }
            asm volatile("cp.async.commit_group;");
        }

        const uint32_t sAst = sA_u + ((c & 3) * HA_STG) * 2;
        const uint32_t sBst = sB_u + ((c & 3) * HB2_STG) * 2;
        #pragma unroll
        for (int ks = 0; ks < 2; ks++) {
            uint32_t afr[4][4];
            #pragma unroll
            for (int mf = 0; mf < 4; mf++) {
                uint32_t addr = sAst + ((wm + mf * 16) * HAP) * 2 + ks * 32 + aOff;
                LDSM_X4(afr[mf][0], afr[mf][1], afr[mf][2], afr[mf][3], addr);
            }
            uint32_t b0_[4], b1_[4];
            #pragma unroll
            for (int p = 0; p < 2; p++) {
                uint32_t addr = sBst + bmOff[p] + ks * (16 * HBP2 * 2);
                LDSM_X4_T(b0_[2*p], b1_[2*p], b0_[2*p+1], b1_[2*p+1], addr);
            }
            #pragma unroll
            for (int nf = 0; nf < 4; nf++)
                #pragma unroll
                for (int mf = 0; mf < 4; mf++)
                    mma_f16(acc[mf][nf], afr[mf], b0_[nf], b1_[nf]);
        }
    }

    #pragma unroll
    for (int mf = 0; mf < 4; mf++) {
        #pragma unroll
        for (int hm = 0; hm < 2; hm++) {
            int r = m0 + wm + mf * 16 + g + hm * 8;
            float bia = bias ? bias[r] : 0.0f;
            __half* crow = Cm + (long long)blockIdx.z * cStride + (long long)r * N;
            float s = 0.0f, q = 0.0f;
            #pragma unroll
            for (int nf = 0; nf < 4; nf++) {
                int cc = n0 + wn + nf * 8 + 2 * tq;
                __half2 hv = __floats2half2_rn(acc[mf][nf][hm * 2 + 0] + bia,
                                               acc[mf][nf][hm * 2 + 1] + bia);
                *(__half2*)(crow + cc) = hv;
                if (stats) {
                    float2 f = __half22float2(hv);
                    s += f.x + f.y;
                    q += f.x * f.x + f.y * f.y;
                }
            }
            if (stats) {
                #pragma unroll
                for (int o = 1; o < 4; o <<= 1) {
                    s += __shfl_xor_sync(0xffffffffu, s, o);
                    q += __shfl_xor_sync(0xffffffffu, q, o);
                }
                if (tq == 0) {
                    atomicAdd_block(&bnS[r - m0], s);
                    atomicAdd_block(&bnQ[r - m0], q);
                }
            }
        }
    }
    if (stats) {
        __syncthreads();
        if (tid < 128) {
            atomicAdd(&stats[m0 + tid], bnS[tid]);
            atomicAdd(&stats[512 + m0 + tid], bnQ[tid]);
        }
    }
}

// ======= fp16 GEMM M=32: block 32x256x32, 3-stage =======
#define HSA_STG (32*HAP)
#define HB_STG (32*HBP)
#define GEMMH32_SMEM (3*(HSA_STG+HB_STG)*2)

__global__ void __launch_bounds__(256, 2) hgemm32_kernel(
    const __half* __restrict__ A, int lda,
    const __half* __restrict__ Bm, long long bStride,
    const float* __restrict__ bias,
    __half* __restrict__ Cm, long long cStride,
    int K, int N)
{
    extern __shared__ __half smh[];
    __half* sA = smh;
    __half* sB = smh + 3 * HSA_STG;
    const uint32_t sA_u = (uint32_t)__cvta_generic_to_shared(sA);
    const uint32_t sB_u = (uint32_t)__cvta_generic_to_shared(sB);

    const int tid = threadIdx.x;
    const int warp = tid >> 5, lane = tid & 31;
    const int g = lane >> 2, tq = lane & 3;
    const int wn = warp * 32;
    const int n0 = blockIdx.x * 256;
    const __half* Bb = Bm + (long long)blockIdx.z * bStride;
    __half* Cb       = Cm + (long long)blockIdx.z * cStride;

    const int aact = (tid < 128);
    const int ar = tid >> 2, acl = (tid & 3) * 8;
    const __half* aSrc = A + (long long)ar * lda + acl;
    const uint32_t adst = (ar * HAP + acl) * 2;

    int brow[4], bdst[4];
    const __half* bSrc[4];
    #pragma unroll
    for (int i = 0; i < 4; i++) {
        int ch = tid + 256 * i;
        brow[i] = ch >> 5;
        int c8 = ch & 31;
        bdst[i] = (brow[i] * HBP + c8 * 8) * 2;
        bSrc[i] = Bb + (long long)brow[i] * N + n0 + c8 * 8;
    }
    const int lsub = lane >> 3, lr = lane & 7;
    const int kl = (lsub & 1) * 8 + lr;
    const int nl = (lsub >> 1) * 8;
    uint32_t bmOff[2];
    #pragma unroll
    for (int p = 0; p < 2; p++)
        bmOff[p] = (uint32_t)((kl * HBP + wn + p * 16 + nl) * 2);
    const uint32_t aOff = (uint32_t)((kl * HAP + nl) * 2);

    const int nch = K >> 5;

    #pragma unroll
    for (int c = 0; c < 2; c++) {
        int kc = c * 32;
        if (aact) cp16(sA_u + (c * HSA_STG) * 2 + adst, aSrc + kc);
        #pragma unroll
        for (int i = 0; i < 4; i++)
            cp16(sB_u + (c * HB_STG) * 2 + bdst[i], bSrc[i] + (long long)kc * N);
        asm volatile("cp.async.commit_group;");
    }

    float acc[2][4][4];
    #pragma unroll
    for (int mf = 0; mf < 2; mf++)
        #pragma unroll
        for (int nf = 0; nf < 4; nf++)
            #pragma unroll
            for (int i = 0; i < 4; i++) acc[mf][nf][i] = 0.0f;

    for (int c = 0; c < nch; c++) {
        if (c + 2 <= nch) asm volatile("cp.async.wait_group 1;");
        else              asm volatile("cp.async.wait_group 0;");
        __syncthreads();

        if (c + 2 < nch) {
            int s = (c + 2) % 3;
            int kc = (c + 2) * 32;
            if (aact) cp16(sA_u + (s * HSA_STG) * 2 + adst, aSrc + kc);
            #pragma unroll
            for (int i = 0; i < 4; i++)
                cp16(sB_u + (s * HB_STG) * 2 + bdst[i], bSrc[i] + (long long)kc * N);
            asm volatile("cp.async.commit_group;");
        }

        const uint32_t sAst = sA_u + ((c % 3) * HSA_STG) * 2;
        const uint32_t sBst = sB_u + ((c % 3) * HB_STG) * 2;
        #pragma unroll
        for (int ks = 0; ks < 2; ks++) {
            uint32_t afr[2][4];
            #pragma unroll
            for (int mf = 0; mf < 2; mf++) {
                uint32_t addr = sAst + ((mf * 16) * HAP) * 2 + ks * 32 + aOff;
                LDSM_X4(afr[mf][0], afr[mf][1], afr[mf][2], afr[mf][3], addr);
            }
            uint32_t b0_[4], b1_[4];
            #pragma unroll
            for (int p = 0; p < 2; p++) {
                uint32_t addr = sBst + bmOff[p] + ks * (16 * HBP * 2);
                LDSM_X4_T(b0_[2*p], b1_[2*p], b0_[2*p+1], b1_[2*p+1], addr);
            }
            #pragma unroll
            for (int nf = 0; nf < 4; nf++)
                #pragma unroll
                for (int mf = 0; mf < 2; mf++)
                    mma_f16(acc[mf][nf], afr[mf], b0_[nf], b1_[nf]);
        }
    }

    #pragma unroll
    for (int mf = 0; mf < 2; mf++) {
        #pragma unroll
        for (int hm = 0; hm < 2; hm++) {
            int r = mf * 16 + g + hm * 8;
            float bia = bias ? bias[r] : 0.0f;
            __half* crow = Cb + (long long)r * N;
            #pragma unroll
            for (int nf = 0; nf < 4; nf++) {
                int cc = n0 + wn + nf * 8 + 2 * tq;
                __half2 hv = __floats2half2_rn(acc[mf][nf][hm * 2 + 0] + bia,
                                               acc[mf][nf][hm * 2 + 1] + bia);
                *(__half2*)(crow + cc) = hv;
            }
        }
    }
}

// ---------------- merged 96x96 transpose (fp16) ----------------
__global__ void transpose16_kernel(const __half* __restrict__ inK, __half* __restrict__ outK,
                                   int nKPlanes,
                                   const __half* __restrict__ inV, __half* __restrict__ outV) {
    __shared__ __half tile[32][33];
    int p = blockIdx.z;
    const __half* in;
    __half* out;
    if (p < nKPlanes) { in = inK + (long)p * 9216; out = outK + (long)p * 9216; }
    else { int q = p - nKPlanes; in = inV + (long)q * 9216; out = outV + (long)q * 9216; }
    int x0 = blockIdx.x * 32, y0 = blockIdx.y * 32;
    int tx = threadIdx.x, ty = threadIdx.y;
    #pragma unroll
    for (int k = 0; k < 4; k++)
        tile[ty + 8*k][tx] = in[(long)(y0 + ty + 8*k) * 96 + x0 + tx];
    __syncthreads();
    #pragma unroll
    for (int k = 0; k < 4; k++)
        out[(long)(x0 + ty + 8*k) * 96 + y0 + tx] = tile[tx][ty + 8*k];
}

// ---------------- qk logits: z=0 eH(diag), z=1 eW ----------------
__global__ void __launch_bounds__(256) qk_kernel(const __half* __restrict__ qt,
                                                 const __half* __restrict__ kt,
                                                 const __half* __restrict__ qb,
                                                 const __half* __restrict__ kb,
                                                 __half* __restrict__ attH,
                                                 __half* __restrict__ attW) {
    int x = blockIdx.x, b = blockIdx.y;
    int diag = (blockIdx.z == 0);
    const __half* qsrc = diag ? qt : qb;
    const __half* ksrc = diag ? kt : kb;
    __half* attX = diag ? attH : attW;
    __shared__ float Qs[32][97], Ks[32][97];
    int tid = threadIdx.x;
    for (int idx = tid; idx < 1536; idx += 256) {
        int ci = idx / 48, i2 = idx % 48;
        long rb = ((long)((b * 32 + ci) * 96 + x)) * 96;
        float2 qa = __half22float2(*(const __half2*)(qsrc + rb + 2 * i2));
        float2 ka = __half22float2(*(const __half2*)(ksrc + rb + 2 * i2));
        Qs[ci][2*i2] = qa.x; Qs[ci][2*i2+1] = qa.y;
        Ks[ci][2*i2] = ka.x; Ks[ci][2*i2+1] = ka.y;
    }
    __syncthreads();
    __half* ab = attX + ((long)(b * 96 + x)) * 9216;
    for (int idx = tid; idx < 2304; idx += 256) {
        int o = idx / 24;
        int P0 = (idx % 24) * 4;
        float acc[4];
        #pragma unroll
        for (int j = 0; j < 4; j++) acc[j] = (diag && (P0 + j == o)) ? NEG_INF_F : 0.0f;
        #pragma unroll
        for (int c = 0; c < 32; c++) {
            float qv = Qs[c][o];
            #pragma unroll
            for (int j = 0; j < 4; j++) acc[j] += qv * Ks[c][P0 + j];
        }
        __half2 h01 = __floats2half2_rn(acc[0], acc[1]);
        __half2 h23 = __floats2half2_rn(acc[2], acc[3]);
        uint2 pk; pk.x = *(uint32_t*)&h01; pk.y = *(uint32_t*)&h23;
        *(uint2*)(ab + o * 96 + P0) = pk;
    }
}

// ------- P*V fp16 mma with fused joint softmax: z=0 H dir, z=1 W dir -------
#define PVP 104
#define PV_SMEM ((96*PVP + 128*PVP) * 2)
__global__ void __launch_bounds__(256) pv_mma_kernel(const __half* __restrict__ vt,
                                                     const __half* __restrict__ vb,
                                                     const __half* __restrict__ attH,
                                                     const __half* __restrict__ attW,
                                                     __half* __restrict__ ohb,
                                                     __half* __restrict__ owb) {
    extern __shared__ __half shh[];
    __half* Ah = shh;
    __half* Vs = shh + 96 * PVP;
    const uint32_t vs_u = (uint32_t)__cvta_generic_to_shared(Vs);
    int x = blockIdx.x, b = blockIdx.y;
    int dirH = (blockIdx.z == 0);
    const __half* Vsrc  = dirH ? vt : vb;
    const __half* attX  = dirH ? attH : attW;
    const __half* attC  = dirH ? attW : attH;   // complementary logits
    __half* outX        = dirH ? ohb : owb;
    int tid = threadIdx.x;
    int warp = tid >> 5, lane = tid & 31;
    int g = lane >> 2, tq = lane & 3;
    int wm = (warp >> 2) * 64;
    int wn = (warp & 3) * 24;
    const int lsub = lane >> 3, lr = lane & 7;
    const uint32_t aOff = (uint32_t)(((((lsub & 1) * 8) + lr) * PVP + (lsub >> 1) * 8) * 2);

    const __half* ab = attX + ((long)(b * 96 + x)) * 9216;
    for (int i4 = tid; i4 < 96 * 12; i4 += 256) {
        int h = i4 / 12, f = i4 % 12;
        uint4 v4 = *(const uint4*)(ab + (long)h * 96 + f * 8);
        *(uint4*)&Ah[h * PVP + f * 8] = v4;
    }
    __syncthreads();

    // fused joint softmax: warp handles rows r = warp + 8*i, lanes cover 3 cols each
    #pragma unroll 1
    for (int i = 0; i < 12; i++) {
        int r = warp + 8 * i;
        const __half* crow = attC + (((long)(b * 96 + r)) * 96 + x) * 96 + lane * 3;
        float cv0 = __half2float(crow[0]);
        float cv1 = __half2float(crow[1]);
        float cv2 = __half2float(crow[2]);
        __half* arow = Ah + r * PVP + lane * 3;
        float av0 = __half2float(arow[0]);
        float av1 = __half2float(arow[1]);
        float av2 = __half2float(arow[2]);
        float m = fmaxf(fmaxf(fmaxf(cv0, cv1), cv2), fmaxf(fmaxf(av0, av1), av2));
        #pragma unroll
        for (int o = 16; o > 0; o >>= 1) m = fmaxf(m, __shfl_xor_sync(0xffffffffu, m, o));
        float e0 = expf(av0 - m), e1 = expf(av1 - m), e2 = expf(av2 - m);
        float s = e0 + e1 + e2 + expf(cv0 - m) + expf(cv1 - m) + expf(cv2 - m);
        #pragma unroll
        for (int o = 16; o > 0; o >>= 1) s += __shfl_xor_sync(0xffffffffu, s, o);
        float inv = 1.0f / s;
        arow[0] = __float2half_rn(e0 * inv);
        arow[1] = __float2half_rn(e1 * inv);
        arow[2] = __float2half_rn(e2 * inv);
    }
    __syncthreads();

    #pragma unroll
    for (int half = 0; half < 2; half++) {
        const __half* vbp = Vsrc + (((long)(b * 256 + half * 128)) * 96 + x) * 96;
        for (int i4 = tid; i4 < 128 * 12; i4 += 256) {
            int ci = i4 / 12, f = i4 % 12;
            uint4 v4 = *(const uint4*)(vbp + (long)ci * 9216 + f * 8);
            *(uint4*)&Vs[ci * PVP + f * 8] = v4;
        }
        __syncthreads();

        float acc[4][3][4];
        #pragma unroll
        for (int mf = 0; mf < 4; mf++)
            #pragma unroll
            for (int nf = 0; nf < 3; nf++)
                #pragma unroll
                for (int i = 0; i < 4; i++) acc[mf][nf][i] = 0.0f;

        #pragma unroll
        for (int ks = 0; ks < 6; ks++) {
            uint32_t afr[4][4];
            #pragma unroll
            for (int mf = 0; mf < 4; mf++) {
                uint32_t addr = vs_u + ((wm + mf * 16) * PVP) * 2 + ks * 32 + aOff;
                LDSM_X4(afr[mf][0], afr[mf][1], afr[mf][2], afr[mf][3], addr);
            }
            #pragma unroll
            for (int nf = 0; nf < 3; nf++) {
                const __half* bb = Ah + (wn + nf * 8 + g) * PVP + ks * 16 + 2 * tq;
                uint32_t b0 = *(const uint32_t*)(bb);
                uint32_t b1 = *(const uint32_t*)(bb + 8);
                #pragma unroll
                for (int mf = 0; mf < 4; mf++)
                    mma_f16(acc[mf][nf], afr[mf], b0, b1);
            }
        }
        __syncthreads();

        #pragma unroll
        for (int mf = 0; mf < 4; mf++) {
            #pragma unroll
            for (int hm = 0; hm < 2; hm++) {
                int c = half * 128 + wm + mf * 16 + g + hm * 8;
                __half* orow = outX + (((long)(b * 256 + c)) * 96 + x) * 96;
                #pragma unroll
                for (int nf = 0; nf < 3; nf++) {
                    int col = wn + nf * 8 + 2 * tq;
                    __half2 hv = __floats2half2_rn(acc[mf][nf][hm * 2 + 0],
                                                   acc[mf][nf][hm * 2 + 1]);
                    *(__half2*)(orow + col) = hv;
                }
            }
        }
    }
}

// ---------------- combine (fp16): dst = g*(ow + ohT^T) + resid ----------------
__global__ void combine_kernel(const __half* __restrict__ ow, const __half* __restrict__ ohT,
                               const __half* __restrict__ resid, const float* __restrict__ gamma_p,
                               __half* __restrict__ dst) {
    __shared__ __half tile[32][33];
    int h0 = blockIdx.x * 32, w0 = blockIdx.y * 32;
    long base = (long)blockIdx.z * 9216;
    int tx = threadIdx.x, ty = threadIdx.y;
    float gm = *gamma_p;
    #pragma unroll
    for (int k = 0; k < 4; k++)
        tile[ty + 8*k][tx] = ohT[base + (long)(w0 + ty + 8*k) * 96 + h0 + tx];
    __syncthreads();
    #pragma unroll
    for (int k = 0; k < 4; k++) {
        long idx = base + (long)(h0 + ty + 8*k) * 96 + w0 + tx;
        float o = gm * (__half2float(ow[idx]) + __half2float(tile[tx][ty + 8*k]))
                + __half2float(resid[idx]);
        dst[idx] = __float2half_rn(o);
    }
}

// ---------------- batchnorm apply: fp16 in -> fp32 out ----------------
__global__ void bn_apply_kernel(const __half* __restrict__ xin, float4* __restrict__ out,
                                const float* __restrict__ stats,
                                const float* __restrict__ scale, const float* __restrict__ bias) {
    const float invN = 1.0f / 73728.0f;
    long total = 8L * 512 * 2304;
    for (long idx = (long)blockIdx.x * blockDim.x + threadIdx.x; idx < total;
         idx += (long)gridDim.x * blockDim.x) {
        int c = (int)((idx / 2304) % 512);
        float mu = stats[c] * invN;
        float var = stats[512 + c] * invN - mu * mu;
        float rs = rsqrtf(var + 1e-5f);
        float sc = scale[c], bi = bias[c];
        uint2 pk = *(const uint2*)(xin + idx * 4);
        float2 f01 = __half22float2(*(__half2*)&pk.x);
        float2 f23 = __half22float2(*(__half2*)&pk.y);
        float4 v;
        v.x = fmaxf((f01.x - mu) * rs * sc + bi, 0.0f);
        v.y = fmaxf((f01.y - mu) * rs * sc + bi, 0.0f);
        v.z = fmaxf((f23.x - mu) * rs * sc + bi, 0.0f);
        v.w = fmaxf((f23.y - mu) * rs * sc + bi, 0.0f);
        out[idx] = v;
    }
}

// ---------------- host ----------------
extern "C" void kernel_launch(void* const* d_in, const int* in_sizes, int n_in,
                              void* d_out, int out_size) {
    const float* low      = (const float*)d_in[0];
    const float* high     = (const float*)d_in[1];
    const float* conv1_w  = (const float*)d_in[2];
    const float* conv1_b  = (const float*)d_in[3];
    const float* conv2_w  = (const float*)d_in[4];
    const float* conv2_b  = (const float*)d_in[5];
    const float* q_w      = (const float*)d_in[6];
    const float* q_b      = (const float*)d_in[7];
    const float* k_w      = (const float*)d_in[8];
    const float* k_b      = (const float*)d_in[9];
    const float* v_w      = (const float*)d_in[10];
    const float* v_b      = (const float*)d_in[11];
    const float* gamma    = (const float*)d_in[12];
    const float* bw       = (const float*)d_in[13];
    const float* bn_scale = (const float*)d_in[14];
    const float* bn_bias  = (const float*)d_in[15];
    float* out = (float*)d_out;

    __half *low16, *hf16, *qf16, *vf16, *vf216, *qb16, *kb16, *qt16, *kt16;
    __half *vb16, *vt16, *attH16, *attW16, *oh16, *ow16, *w16;
    float* statsp;
    cudaGetSymbolAddress((void**)&low16, g_low16);
    cudaGetSymbolAddress((void**)&hf16,  g_hf16);
    cudaGetSymbolAddress((void**)&qf16,  g_qf16);
    cudaGetSymbolAddress((void**)&vf16,  g_vf16);
    cudaGetSymbolAddress((void**)&vf216, g_vf216);
    cudaGetSymbolAddress((void**)&qb16,  g_qb16);
    cudaGetSymbolAddress((void**)&kb16,  g_kb16);
    cudaGetSymbolAddress((void**)&qt16,  g_qt16);
    cudaGetSymbolAddress((void**)&kt16,  g_kt16);
    cudaGetSymbolAddress((void**)&vb16,  g_vb16);
    cudaGetSymbolAddress((void**)&vt16,  g_vt16);
    cudaGetSymbolAddress((void**)&attH16, g_attH16);
    cudaGetSymbolAddress((void**)&attW16, g_attW16);
    cudaGetSymbolAddress((void**)&oh16,  g_oh16);
    cudaGetSymbolAddress((void**)&ow16,  g_ow16);
    cudaGetSymbolAddress((void**)&w16,   g_w16);
    cudaGetSymbolAddress((void**)&statsp, g_stats);

    cudaFuncSetAttribute(hgemm_kernel,   cudaFuncAttributeMaxDynamicSharedMemorySize, GEMMH_SMEM);
    cudaFuncSetAttribute(hgemm32_kernel, cudaFuncAttributeMaxDynamicSharedMemorySize, GEMMH32_SMEM);
    cudaFuncSetAttribute(pv_mma_kernel,  cudaFuncAttributeMaxDynamicSharedMemorySize, PV_SMEM);

    wcvt_kernel<<<720, 256>>>(conv1_w, conv2_w, v_w, k_w, q_w, bw, w16);
    resize_kernel<<<4096, 256>>>(high, hf16, low, low16, statsp);

    // conv1 -> qf16 ; conv2 -> vf16
    hgemm_kernel<<<dim3(72, 2, 8), 256, GEMMH_SMEM>>>(
        w16 + W_C1, 512, low16, 512LL * 9216, nullptr, 0, 1 << 30,
        conv1_b, qf16, 256LL * 9216, 512, 9216, nullptr);
    hgemm_kernel<<<dim3(72, 2, 8), 256, GEMMH_SMEM>>>(
        w16 + W_C2, 512, hf16, 512LL * 9216, nullptr, 0, 1 << 30,
        conv2_b, vf16, 256LL * 9216, 512, 9216, nullptr);
    hgemm32_kernel<<<dim3(36, 1, 8), 256, GEMMH32_SMEM>>>(
        w16 + W_Q, 256, qf16, 256LL * 9216, q_b, qb16, 32LL * 9216, 256, 9216);
    transpose16_kernel<<<dim3(3, 3, 256), dim3(32, 8)>>>(qb16, qt16, 256, qb16, qt16);

    for (int it = 0; it < 2; it++) {
        const __half* src = it ? vf216 : vf16;
        __half* dstp      = it ? vf16  : vf216;
        hgemm32_kernel<<<dim3(36, 1, 8), 256, GEMMH32_SMEM>>>(
            w16 + W_K, 256, src, 256LL * 9216, k_b, kb16, 32LL * 9216, 256, 9216);
        hgemm_kernel<<<dim3(72, 2, 8), 256, GEMMH_SMEM>>>(
            w16 + W_V, 256, src, 256LL * 9216, nullptr, 0, 1 << 30,
            v_b, vb16, 256LL * 9216, 256, 9216, nullptr);
        transpose16_kernel<<<dim3(3, 3, 2304), dim3(32, 8)>>>(kb16, kt16, 256, vb16, vt16);
        qk_kernel<<<dim3(96, 8, 2), 256>>>(qt16, kt16, qb16, kb16, attH16, attW16);
        pv_mma_kernel<<<dim3(96, 8, 2), 256, PV_SMEM>>>(vt16, vb16, attH16, attW16, oh16, ow16);
        combine_kernel<<<dim3(3, 3, 2048), dim3(32, 8)>>>(ow16, oh16, src, gamma, dstp);
    }

    // bottleneck: K=768 fp16 -> fp16 scratch (low16, long dead) + fused BN stats
    hgemm_kernel<<<dim3(72, 4, 8), 256, GEMMH_SMEM>>>(
        w16 + W_BW, 768, vf16, 256LL * 9216, hf16, 512LL * 9216, 256,
        nullptr, low16, 512LL * 9216, 768, 9216, statsp);

    // batchnorm + relu: fp16 in -> fp32 out
    bn_apply_kernel<<<4608, 256>>>(low16, (float4*)out, statsp, bn_scale, bn_bias);
}

// round 15
// speedup vs baseline: 1.0591x; 1.0591x over previous
#include <cuda_runtime.h>
#include <cuda_fp16.h>
#include <cstdint>

#define NEG_INF_F (-1000000000.0f)

// ---------------- scratch (halves) ----------------
__device__ __half g_low16[37748736];
__device__ __half g_hf16 [37748736];
__device__ __half g_qf16 [18874368];
__device__ __half g_vf16 [18874368];
__device__ __half g_vf216[18874368];
__device__ __half g_qb16 [2359296];
__device__ __half g_kb16 [2359296];
__device__ __half g_qt16 [2359296];
__device__ __half g_kt16 [2359296];
__device__ __half g_vb16 [18874368];
__device__ __half g_vt16 [18874368];
__device__ __half g_attH16[7077888];
__device__ __half g_attW16[7077888];
__device__ __half g_oh16 [18874368];
__device__ __half g_ow16 [18874368];
__device__ __half g_w16  [737280];
__device__ float  g_stats[1024];

#define W_C1 0
#define W_C2 131072
#define W_V  262144
#define W_K  327680
#define W_Q  335872
#define W_BW 344064

__global__ void wcvt_kernel(const float* c1, const float* c2, const float* vw,
                            const float* kw, const float* qw, const float* bw,
                            __half* w16) {
    for (int i = blockIdx.x * blockDim.x + threadIdx.x; i < 737280;
         i += gridDim.x * blockDim.x) {
        float v;
        if (i < W_C2) v = c1[i];
        else if (i < W_V) v = c2[i - W_C2];
        else if (i < W_K) v = vw[i - W_V];
        else if (i < W_Q) v = kw[i - W_K];
        else if (i < W_BW) v = qw[i - W_Q];
        else v = bw[i - W_BW];
        w16[i] = __float2half_rn(v);
    }
}

// resize high->hf16 (bilinear 2x), convert low->low16, zero stats
__global__ void resize_kernel(const float* __restrict__ in, __half* __restrict__ out,
                              const float* __restrict__ low, __half* __restrict__ low16,
                              float* __restrict__ stats) {
    long gtid = (long)blockIdx.x * blockDim.x + threadIdx.x;
    if (gtid < 1024) stats[gtid] = 0.0f;
    long total4 = 8L * 512 * 96 * 24;
    for (long idx = gtid; idx < total4; idx += (long)gridDim.x * blockDim.x) {
        int ox0 = (int)(idx % 24) * 4;
        long t  = idx / 24;
        int oy = (int)(t % 96);
        long bc = t / 96;
        int my = oy >> 1;
        int y0, y1; float wy0;
        if (oy & 1) { y0 = my; y1 = (my < 47) ? my + 1 : 47; wy0 = 0.75f; }
        else        { y0 = (my > 0) ? my - 1 : 0; y1 = my;   wy0 = 0.25f; }
        const float* p = in + bc * 2304;
        float r[4];
        #pragma unroll
        for (int j = 0; j < 4; j++) {
            int ox = ox0 + j, mx = ox >> 1;
            int x0, x1; float wx0;
            if (ox & 1) { x0 = mx; x1 = (mx < 47) ? mx + 1 : 47; wx0 = 0.75f; }
            else        { x0 = (mx > 0) ? mx - 1 : 0; x1 = mx;   wx0 = 0.25f; }
            float top = wx0 * p[y0*48+x0] + (1.f-wx0) * p[y0*48+x1];
            float bot = wx0 * p[y1*48+x0] + (1.f-wx0) * p[y1*48+x1];
            r[j] = wy0 * top + (1.f-wy0) * bot;
        }
        __half2 h01 = __floats2half2_rn(r[0], r[1]);
        __half2 h23 = __floats2half2_rn(r[2], r[3]);
        uint2 pk; pk.x = *(uint32_t*)&h01; pk.y = *(uint32_t*)&h23;
        *(uint2*)(out + idx * 4) = pk;
    }
    long totalL = 37748736L / 4;
    for (long idx = gtid; idx < totalL; idx += (long)gridDim.x * blockDim.x) {
        float4 v = *(const float4*)(low + idx * 4);
        __half2 h01 = __floats2half2_rn(v.x, v.y);
        __half2 h23 = __floats2half2_rn(v.z, v.w);
        uint2 pk; pk.x = *(uint32_t*)&h01; pk.y = *(uint32_t*)&h23;
        *(uint2*)(low16 + idx * 4) = pk;
    }
}

__device__ __forceinline__ void cp16(uint32_t dst, const void* src) {
    asm volatile("cp.async.cg.shared.global [%0], [%1], 16;"
                 :: "r"(dst), "l"(src));
}
__device__ __forceinline__ void mma_f16(float* c, const uint32_t* a, uint32_t b0, uint32_t b1) {
    asm volatile("mma.sync.aligned.m16n8k16.row.col.f32.f16.f16.f32 "
                 "{%0,%1,%2,%3}, {%4,%5,%6,%7}, {%8,%9}, {%0,%1,%2,%3};"
                 : "+f"(c[0]), "+f"(c[1]), "+f"(c[2]), "+f"(c[3])
                 : "r"(a[0]), "r"(a[1]), "r"(a[2]), "r"(a[3]), "r"(b0), "r"(b1));
}
#define LDSM_X4(r0, r1, r2, r3, addr) \
    asm volatile("ldmatrix.sync.aligned.m8n8.x4.shared.b16 {%0,%1,%2,%3}, [%4];" \
                 : "=r"(r0), "=r"(r1), "=r"(r2), "=r"(r3) : "r"(addr))
#define LDSM_X4_T(r0, r1, r2, r3, addr) \
    asm volatile("ldmatrix.sync.aligned.m8n8.x4.trans.shared.b16 {%0,%1,%2,%3}, [%4];" \
                 : "=r"(r0), "=r"(r1), "=r"(r2), "=r"(r3) : "r"(addr))

#define HAP 40
#define HBP 264      // hgemm32 (N-tile 256)
#define HBP2 136     // hgemm   (N-tile 128)

// ======= fp16 GEMM: block 128x128x32, warp 64x32, 4-stage, 2 CTAs/SM =======
#define HA_STG (128*HAP)
#define HB2_STG (32*HBP2)
#define GEMMH_SMEM (4*(HA_STG+HB2_STG)*2)

__global__ void __launch_bounds__(256, 2) hgemm_kernel(
    const __half* __restrict__ A, int lda,
    const __half* __restrict__ B1, long long b1s,
    const __half* __restrict__ B2, long long b2s, int kSplit,
    const float* __restrict__ bias,
    __half* __restrict__ Cm, long long cStride,
    int K, int N, float* __restrict__ stats)
{
    extern __shared__ __half smh[];
    __half* sA = smh;
    __half* sB = smh + 4 * HA_STG;
    const uint32_t sA_u = (uint32_t)__cvta_generic_to_shared(sA);
    const uint32_t sB_u = (uint32_t)__cvta_generic_to_shared(sB);
    __shared__ float bnS[128], bnQ[128];

    const int tid = threadIdx.x;
    if (tid < 128) { bnS[tid] = 0.0f; bnQ[tid] = 0.0f; }
    const int warp = tid >> 5, lane = tid & 31;
    const int g = lane >> 2, tq = lane & 3;
    const int wm = (warp >> 2) * 64;
    const int wn = (warp & 3) * 32;
    const int m0 = blockIdx.y * 128;
    const int n0 = blockIdx.x * 128;
    const __half* B1b = B1 + (long long)blockIdx.z * b1s;
    const __half* B2b = B2 ? (B2 + (long long)blockIdx.z * b2s) : B1b;
    const bool split = (B2 != nullptr);

    int arow[2], acol[2];
    const __half* aSrc[2];
    #pragma unroll
    for (int i = 0; i < 2; i++) {
        int ch = tid + 256 * i;
        arow[i] = ch >> 2;  acol[i] = (ch & 3) * 8;
        aSrc[i] = A + (long long)(m0 + arow[i]) * lda + acol[i];
    }
    int brow[2], bnoff[2], bdst[2];
    const __half* bSrcBase[2];
    #pragma unroll
    for (int i = 0; i < 2; i++) {
        int ch = tid + 256 * i;
        brow[i] = ch >> 4;
        int c8 = ch & 15;
        bnoff[i] = n0 + c8 * 8;
        bdst[i] = (brow[i] * HBP2 + c8 * 8) * 2;
        bSrcBase[i] = B1b + (long long)brow[i] * N + bnoff[i];
    }
    const int lsub = lane >> 3, lr = lane & 7;
    const int kl = (lsub & 1) * 8 + lr;
    const int nl = (lsub >> 1) * 8;
    uint32_t bmOff[2];
    #pragma unroll
    for (int p = 0; p < 2; p++)
        bmOff[p] = (uint32_t)((kl * HBP2 + wn + p * 16 + nl) * 2);
    const uint32_t aOff = (uint32_t)((kl * HAP + nl) * 2);

    const int nch = K >> 5;

    #pragma unroll
    for (int c = 0; c < 3; c++) {
        int kc = c * 32;
        uint32_t da = sA_u + (c * HA_STG) * 2;
        uint32_t db = sB_u + (c * HB2_STG) * 2;
        #pragma unroll
        for (int i = 0; i < 2; i++)
            cp16(da + (arow[i] * HAP + acol[i]) * 2, aSrc[i] + kc);
        if (split) {
            #pragma unroll
            for (int i = 0; i < 2; i++) {
                int row = kc + brow[i];
                const __half* src = (row < kSplit) ? (B1b + (long long)row * N + bnoff[i])
                                                   : (B2b + (long long)(row - kSplit) * N + bnoff[i]);
                cp16(db + bdst[i], src);
            }
        } else {
            #pragma unroll
            for (int i = 0; i < 2; i++)
                cp16(db + bdst[i], bSrcBase[i] + (long long)kc * N);
        }
        asm volatile("cp.async.commit_group;");
    }

    float acc[4][4][4];
    #pragma unroll
    for (int mf = 0; mf < 4; mf++)
        #pragma unroll
        for (int nf = 0; nf < 4; nf++)
            #pragma unroll
            for (int i = 0; i < 4; i++) acc[mf][nf][i] = 0.0f;

    for (int c = 0; c < nch; c++) {
        if (c + 3 <= nch)      asm volatile("cp.async.wait_group 2;");
        else if (c + 2 == nch) asm volatile("cp.async.wait_group 1;");
        else                   asm volatile("cp.async.wait_group 0;");
        __syncthreads();

        if (c + 3 < nch) {
            int s = (c + 3) & 3;
            int kc = (c + 3) * 32;
            uint32_t da = sA_u + (s * HA_STG) * 2;
            uint32_t db = sB_u + (s * HB2_STG) * 2;
            #pragma unroll
            for (int i = 0; i < 2; i++)
                cp16(da + (arow[i] * HAP + acol[i]) * 2, aSrc[i] + kc);
            if (split) {
                #pragma unroll
                for (int i = 0; i < 2; i++) {
                    int row = kc + brow[i];
                    const __half* src = (row < kSplit) ? (B1b + (long long)row * N + bnoff[i])
                                                       : (B2b + (long long)(row - kSplit) * N + bnoff[i]);
                    cp16(db + bdst[i], src);
                }
            } else {
                #pragma unroll
                for (int i = 0; i < 2; i++)
                    cp16(db + bdst[i], bSrcBase[i] + (long long)kc * N);
            }
            asm volatile("cp.async.commit_group;");
        }

        const uint32_t sAst = sA_u + ((c & 3) * HA_STG) * 2;
        const uint32_t sBst = sB_u + ((c & 3) * HB2_STG) * 2;
        #pragma unroll
        for (int ks = 0; ks < 2; ks++) {
            uint32_t afr[4][4];
            #pragma unroll
            for (int mf = 0; mf < 4; mf++) {
                uint32_t addr = sAst + ((wm + mf * 16) * HAP) * 2 + ks * 32 + aOff;
                LDSM_X4(afr[mf][0], afr[mf][1], afr[mf][2], afr[mf][3], addr);
            }
            uint32_t b0_[4], b1_[4];
            #pragma unroll
            for (int p = 0; p < 2; p++) {
                uint32_t addr = sBst + bmOff[p] + ks * (16 * HBP2 * 2);
                LDSM_X4_T(b0_[2*p], b1_[2*p], b0_[2*p+1], b1_[2*p+1], addr);
            }
            #pragma unroll
            for (int nf = 0; nf < 4; nf++)
                #pragma unroll
                for (int mf = 0; mf < 4; mf++)
                    mma_f16(acc[mf][nf], afr[mf], b0_[nf], b1_[nf]);
        }
    }

    #pragma unroll
    for (int mf = 0; mf < 4; mf++) {
        #pragma unroll
        for (int hm = 0; hm < 2; hm++) {
            int r = m0 + wm + mf * 16 + g + hm * 8;
            float bia = bias ? bias[r] : 0.0f;
            __half* crow = Cm + (long long)blockIdx.z * cStride + (long long)r * N;
            float s = 0.0f, q = 0.0f;
            #pragma unroll
            for (int nf = 0; nf < 4; nf++) {
                int cc = n0 + wn + nf * 8 + 2 * tq;
                __half2 hv = __floats2half2_rn(acc[mf][nf][hm * 2 + 0] + bia,
                                               acc[mf][nf][hm * 2 + 1] + bia);
                *(__half2*)(crow + cc) = hv;
                if (stats) {
                    float2 f = __half22float2(hv);
                    s += f.x + f.y;
                    q += f.x * f.x + f.y * f.y;
                }
            }
            if (stats) {
                #pragma unroll
                for (int o = 1; o < 4; o <<= 1) {
                    s += __shfl_xor_sync(0xffffffffu, s, o);
                    q += __shfl_xor_sync(0xffffffffu, q, o);
                }
                if (tq == 0) {
                    atomicAdd_block(&bnS[r - m0], s);
                    atomicAdd_block(&bnQ[r - m0], q);
                }
            }
        }
    }
    if (stats) {
        __syncthreads();
        if (tid < 128) {
            atomicAdd(&stats[m0 + tid], bnS[tid]);
            atomicAdd(&stats[512 + m0 + tid], bnQ[tid]);
        }
    }
}

// ======= fp16 GEMM M=32: block 32x256x32, 3-stage =======
#define HSA_STG (32*HAP)
#define HB_STG (32*HBP)
#define GEMMH32_SMEM (3*(HSA_STG+HB_STG)*2)

__global__ void __launch_bounds__(256, 2) hgemm32_kernel(
    const __half* __restrict__ A, int lda,
    const __half* __restrict__ Bm, long long bStride,
    const float* __restrict__ bias,
    __half* __restrict__ Cm, long long cStride,
    int K, int N)
{
    extern __shared__ __half smh[];
    __half* sA = smh;
    __half* sB = smh + 3 * HSA_STG;
    const uint32_t sA_u = (uint32_t)__cvta_generic_to_shared(sA);
    const uint32_t sB_u = (uint32_t)__cvta_generic_to_shared(sB);

    const int tid = threadIdx.x;
    const int warp = tid >> 5, lane = tid & 31;
    const int g = lane >> 2, tq = lane & 3;
    const int wn = warp * 32;
    const int n0 = blockIdx.x * 256;
    const __half* Bb = Bm + (long long)blockIdx.z * bStride;
    __half* Cb       = Cm + (long long)blockIdx.z * cStride;

    const int aact = (tid < 128);
    const int ar = tid >> 2, acl = (tid & 3) * 8;
    const __half* aSrc = A + (long long)ar * lda + acl;
    const uint32_t adst = (ar * HAP + acl) * 2;

    int brow[4], bdst[4];
    const __half* bSrc[4];
    #pragma unroll
    for (int i = 0; i < 4; i++) {
        int ch = tid + 256 * i;
        brow[i] = ch >> 5;
        int c8 = ch & 31;
        bdst[i] = (brow[i] * HBP + c8 * 8) * 2;
        bSrc[i] = Bb + (long long)brow[i] * N + n0 + c8 * 8;
    }
    const int lsub = lane >> 3, lr = lane & 7;
    const int kl = (lsub & 1) * 8 + lr;
    const int nl = (lsub >> 1) * 8;
    uint32_t bmOff[2];
    #pragma unroll
    for (int p = 0; p < 2; p++)
        bmOff[p] = (uint32_t)((kl * HBP + wn + p * 16 + nl) * 2);
    const uint32_t aOff = (uint32_t)((kl * HAP + nl) * 2);

    const int nch = K >> 5;

    #pragma unroll
    for (int c = 0; c < 2; c++) {
        int kc = c * 32;
        if (aact) cp16(sA_u + (c * HSA_STG) * 2 + adst, aSrc + kc);
        #pragma unroll
        for (int i = 0; i < 4; i++)
            cp16(sB_u + (c * HB_STG) * 2 + bdst[i], bSrc[i] + (long long)kc * N);
        asm volatile("cp.async.commit_group;");
    }

    float acc[2][4][4];
    #pragma unroll
    for (int mf = 0; mf < 2; mf++)
        #pragma unroll
        for (int nf = 0; nf < 4; nf++)
            #pragma unroll
            for (int i = 0; i < 4; i++) acc[mf][nf][i] = 0.0f;

    for (int c = 0; c < nch; c++) {
        if (c + 2 <= nch) asm volatile("cp.async.wait_group 1;");
        else              asm volatile("cp.async.wait_group 0;");
        __syncthreads();

        if (c + 2 < nch) {
            int s = (c + 2) % 3;
            int kc = (c + 2) * 32;
            if (aact) cp16(sA_u + (s * HSA_STG) * 2 + adst, aSrc + kc);
            #pragma unroll
            for (int i = 0; i < 4; i++)
                cp16(sB_u + (s * HB_STG) * 2 + bdst[i], bSrc[i] + (long long)kc * N);
            asm volatile("cp.async.commit_group;");
        }

        const uint32_t sAst = sA_u + ((c % 3) * HSA_STG) * 2;
        const uint32_t sBst = sB_u + ((c % 3) * HB_STG) * 2;
        #pragma unroll
        for (int ks = 0; ks < 2; ks++) {
            uint32_t afr[2][4];
            #pragma unroll
            for (int mf = 0; mf < 2; mf++) {
                uint32_t addr = sAst + ((mf * 16) * HAP) * 2 + ks * 32 + aOff;
                LDSM_X4(afr[mf][0], afr[mf][1], afr[mf][2], afr[mf][3], addr);
            }
            uint32_t b0_[4], b1_[4];
            #pragma unroll
            for (int p = 0; p < 2; p++) {
                uint32_t addr = sBst + bmOff[p] + ks * (16 * HBP * 2);
                LDSM_X4_T(b0_[2*p], b1_[2*p], b0_[2*p+1], b1_[2*p+1], addr);
            }
            #pragma unroll
            for (int nf = 0; nf < 4; nf++)
                #pragma unroll
                for (int mf = 0; mf < 2; mf++)
                    mma_f16(acc[mf][nf], afr[mf], b0_[nf], b1_[nf]);
        }
    }

    #pragma unroll
    for (int mf = 0; mf < 2; mf++) {
        #pragma unroll
        for (int hm = 0; hm < 2; hm++) {
            int r = mf * 16 + g + hm * 8;
            float bia = bias ? bias[r] : 0.0f;
            __half* crow = Cb + (long long)r * N;
            #pragma unroll
            for (int nf = 0; nf < 4; nf++) {
                int cc = n0 + wn + nf * 8 + 2 * tq;
                __half2 hv = __floats2half2_rn(acc[mf][nf][hm * 2 + 0] + bia,
                                               acc[mf][nf][hm * 2 + 1] + bia);
                *(__half2*)(crow + cc) = hv;
            }
        }
    }
}

// ---------------- merged 96x96 transpose (fp16) ----------------
__global__ void transpose16_kernel(const __half* __restrict__ inK, __half* __restrict__ outK,
                                   int nKPlanes,
                                   const __half* __restrict__ inV, __half* __restrict__ outV) {
    __shared__ __half tile[32][33];
    int p = blockIdx.z;
    const __half* in;
    __half* out;
    if (p < nKPlanes) { in = inK + (long)p * 9216; out = outK + (long)p * 9216; }
    else { int q = p - nKPlanes; in = inV + (long)q * 9216; out = outV + (long)q * 9216; }
    int x0 = blockIdx.x * 32, y0 = blockIdx.y * 32;
    int tx = threadIdx.x, ty = threadIdx.y;
    #pragma unroll
    for (int k = 0; k < 4; k++)
        tile[ty + 8*k][tx] = in[(long)(y0 + ty + 8*k) * 96 + x0 + tx];
    __syncthreads();
    #pragma unroll
    for (int k = 0; k < 4; k++)
        out[(long)(x0 + ty + 8*k) * 96 + y0 + tx] = tile[tx][ty + 8*k];
}

// ---------------- qk logits: z=0 eH(diag), z=1 eW ----------------
__global__ void __launch_bounds__(256) qk_kernel(const __half* __restrict__ qt,
                                                 const __half* __restrict__ kt,
                                                 const __half* __restrict__ qb,
                                                 const __half* __restrict__ kb,
                                                 __half* __restrict__ attH,
                                                 __half* __restrict__ attW) {
    int x = blockIdx.x, b = blockIdx.y;
    int diag = (blockIdx.z == 0);
    const __half* qsrc = diag ? qt : qb;
    const __half* ksrc = diag ? kt : kb;
    __half* attX = diag ? attH : attW;
    __shared__ float Qs[32][97], Ks[32][97];
    int tid = threadIdx.x;
    for (int idx = tid; idx < 1536; idx += 256) {
        int ci = idx / 48, i2 = idx % 48;
        long rb = ((long)((b * 32 + ci) * 96 + x)) * 96;
        float2 qa = __half22float2(*(const __half2*)(qsrc + rb + 2 * i2));
        float2 ka = __half22float2(*(const __half2*)(ksrc + rb + 2 * i2));
        Qs[ci][2*i2] = qa.x; Qs[ci][2*i2+1] = qa.y;
        Ks[ci][2*i2] = ka.x; Ks[ci][2*i2+1] = ka.y;
    }
    __syncthreads();
    __half* ab = attX + ((long)(b * 96 + x)) * 9216;
    for (int idx = tid; idx < 2304; idx += 256) {
        int o = idx / 24;
        int P0 = (idx % 24) * 4;
        float acc[4];
        #pragma unroll
        for (int j = 0; j < 4; j++) acc[j] = (diag && (P0 + j == o)) ? NEG_INF_F : 0.0f;
        #pragma unroll
        for (int c = 0; c < 32; c++) {
            float qv = Qs[c][o];
            #pragma unroll
            for (int j = 0; j < 4; j++) acc[j] += qv * Ks[c][P0 + j];
        }
        __half2 h01 = __floats2half2_rn(acc[0], acc[1]);
        __half2 h23 = __floats2half2_rn(acc[2], acc[3]);
        uint2 pk; pk.x = *(uint32_t*)&h01; pk.y = *(uint32_t*)&h23;
        *(uint2*)(ab + o * 96 + P0) = pk;
    }
}

// ---------------- joint softmax (fp16) ----------------
__global__ void softmax2_kernel(__half* __restrict__ attH, __half* __restrict__ attW) {
    int row = blockIdx.x * 8 + threadIdx.y;
    int b = row / 9216, rem = row % 9216, h = rem / 96, w = rem % 96;
    __half* pH = attH + ((long)(b * 96 + w) * 96 + h) * 96;
    __half* pW = attW + ((long)(b * 96 + h) * 96 + w) * 96;
    int lane = threadIdx.x;
    float v[6];
    #pragma unroll
    for (int j = 0; j < 3; j++) v[j]     = __half2float(pH[j * 32 + lane]);
    #pragma unroll
    for (int j = 0; j < 3; j++) v[3 + j] = __half2float(pW[j * 32 + lane]);
    float m = -3.0e38f;
    #pragma unroll
    for (int j = 0; j < 6; j++) m = fmaxf(m, v[j]);
    #pragma unroll
    for (int o = 16; o > 0; o >>= 1) m = fmaxf(m, __shfl_xor_sync(0xffffffffu, m, o));
    float s = 0.0f;
    #pragma unroll
    for (int j = 0; j < 6; j++) { v[j] = expf(v[j] - m); s += v[j]; }
    #pragma unroll
    for (int o = 16; o > 0; o >>= 1) s += __shfl_xor_sync(0xffffffffu, s, o);
    float inv = 1.0f / s;
    #pragma unroll
    for (int j = 0; j < 3; j++) pH[j * 32 + lane] = __float2half_rn(v[j] * inv);
    #pragma unroll
    for (int j = 0; j < 3; j++) pW[j * 32 + lane] = __float2half_rn(v[3 + j] * inv);
}

// ---------------- P*V fp16 mma: z=0 H dir, z=1 W dir ----------------
#define PVP 104
#define PV_SMEM ((96*PVP + 128*PVP) * 2)
__global__ void __launch_bounds__(256) pv_mma_kernel(const __half* __restrict__ vt,
                                                     const __half* __restrict__ vb,
                                                     const __half* __restrict__ attH,
                                                     const __half* __restrict__ attW,
                                                     __half* __restrict__ ohb,
                                                     __half* __restrict__ owb) {
    extern __shared__ __half shh[];
    __half* Ah = shh;
    __half* Vs = shh + 96 * PVP;
    const uint32_t vs_u = (uint32_t)__cvta_generic_to_shared(Vs);
    int x = blockIdx.x, b = blockIdx.y;
    int dirH = (blockIdx.z == 0);
    const __half* Vsrc = dirH ? vt : vb;
    const __half* attX = dirH ? attH : attW;
    __half* outX       = dirH ? ohb : owb;
    int tid = threadIdx.x;
    int warp = tid >> 5, lane = tid & 31;
    int g = lane >> 2, tq = lane & 3;
    int wm = (warp >> 2) * 64;
    int wn = (warp & 3) * 24;
    const int lsub = lane >> 3, lr = lane & 7;
    const uint32_t aOff = (uint32_t)(((((lsub & 1) * 8) + lr) * PVP + (lsub >> 1) * 8) * 2);

    const __half* ab = attX + ((long)(b * 96 + x)) * 9216;
    for (int i4 = tid; i4 < 96 * 12; i4 += 256) {
        int h = i4 / 12, f = i4 % 12;
        uint4 v4 = *(const uint4*)(ab + (long)h * 96 + f * 8);
        *(uint4*)&Ah[h * PVP + f * 8] = v4;
    }

    #pragma unroll
    for (int half = 0; half < 2; half++) {
        const __half* vbp = Vsrc + (((long)(b * 256 + half * 128)) * 96 + x) * 96;
        for (int i4 = tid; i4 < 128 * 12; i4 += 256) {
            int ci = i4 / 12, f = i4 % 12;
            uint4 v4 = *(const uint4*)(vbp + (long)ci * 9216 + f * 8);
            *(uint4*)&Vs[ci * PVP + f * 8] = v4;
        }
        __syncthreads();

        float acc[4][3][4];
        #pragma unroll
        for (int mf = 0; mf < 4; mf++)
            #pragma unroll
            for (int nf = 0; nf < 3; nf++)
                #pragma unroll
                for (int i = 0; i < 4; i++) acc[mf][nf][i] = 0.0f;

        #pragma unroll
        for (int ks = 0; ks < 6; ks++) {
            uint32_t afr[4][4];
            #pragma unroll
            for (int mf = 0; mf < 4; mf++) {
                uint32_t addr = vs_u + ((wm + mf * 16) * PVP) * 2 + ks * 32 + aOff;
                LDSM_X4(afr[mf][0], afr[mf][1], afr[mf][2], afr[mf][3], addr);
            }
            #pragma unroll
            for (int nf = 0; nf < 3; nf++) {
                const __half* bb = Ah + (wn + nf * 8 + g) * PVP + ks * 16 + 2 * tq;
                uint32_t b0 = *(const uint32_t*)(bb);
                uint32_t b1 = *(const uint32_t*)(bb + 8);
                #pragma unroll
                for (int mf = 0; mf < 4; mf++)
                    mma_f16(acc[mf][nf], afr[mf], b0, b1);
            }
        }
        __syncthreads();

        #pragma unroll
        for (int mf = 0; mf < 4; mf++) {
            #pragma unroll
            for (int hm = 0; hm < 2; hm++) {
                int c = half * 128 + wm + mf * 16 + g + hm * 8;
                __half* orow = outX + (((long)(b * 256 + c)) * 96 + x) * 96;
                #pragma unroll
                for (int nf = 0; nf < 3; nf++) {
                    int col = wn + nf * 8 + 2 * tq;
                    __half2 hv = __floats2half2_rn(acc[mf][nf][hm * 2 + 0],
                                                   acc[mf][nf][hm * 2 + 1]);
                    *(__half2*)(orow + col) = hv;
                }
            }
        }
    }
}

// ---------------- combine (fp16): dst = g*(ow + ohT^T) + resid ----------------
__global__ void combine_kernel(const __half* __restrict__ ow, const __half* __restrict__ ohT,
                               const __half* __restrict__ resid, const float* __restrict__ gamma_p,
                               __half* __restrict__ dst) {
    __shared__ __half tile[32][33];
    int h0 = blockIdx.x * 32, w0 = blockIdx.y * 32;
    long base = (long)blockIdx.z * 9216;
    int tx = threadIdx.x, ty = threadIdx.y;
    float gm = *gamma_p;
    #pragma unroll
    for (int k = 0; k < 4; k++)
        tile[ty + 8*k][tx] = ohT[base + (long)(w0 + ty + 8*k) * 96 + h0 + tx];
    __syncthreads();
    #pragma unroll
    for (int k = 0; k < 4; k++) {
        long idx = base + (long)(h0 + ty + 8*k) * 96 + w0 + tx;
        float o = gm * (__half2float(ow[idx]) + __half2float(tile[tx][ty + 8*k]))
                + __half2float(resid[idx]);
        dst[idx] = __float2half_rn(o);
    }
}

// ---------------- batchnorm apply: fp16 in -> fp32 out ----------------
__global__ void bn_apply_kernel(const __half* __restrict__ xin, float4* __restrict__ out,
                                const float* __restrict__ stats,
                                const float* __restrict__ scale, const float* __restrict__ bias) {
    const float invN = 1.0f / 73728.0f;
    long total = 8L * 512 * 2304;
    for (long idx = (long)blockIdx.x * blockDim.x + threadIdx.x; idx < total;
         idx += (long)gridDim.x * blockDim.x) {
        int c = (int)((idx / 2304) % 512);
        float mu = stats[c] * invN;
        float var = stats[512 + c] * invN - mu * mu;
        float rs = rsqrtf(var + 1e-5f);
        float sc = scale[c], bi = bias[c];
        uint2 pk = *(const uint2*)(xin + idx * 4);
        float2 f01 = __half22float2(*(__half2*)&pk.x);
        float2 f23 = __half22float2(*(__half2*)&pk.y);
        float4 v;
        v.x = fmaxf((f01.x - mu) * rs * sc + bi, 0.0f);
        v.y = fmaxf((f01.y - mu) * rs * sc + bi, 0.0f);
        v.z = fmaxf((f23.x - mu) * rs * sc + bi, 0.0f);
        v.w = fmaxf((f23.y - mu) * rs * sc + bi, 0.0f);
        out[idx] = v;
    }
}

// ---------------- host ----------------
extern "C" void kernel_launch(void* const* d_in, const int* in_sizes, int n_in,
                              void* d_out, int out_size) {
    const float* low      = (const float*)d_in[0];
    const float* high     = (const float*)d_in[1];
    const float* conv1_w  = (const float*)d_in[2];
    const float* conv1_b  = (const float*)d_in[3];
    const float* conv2_w  = (const float*)d_in[4];
    const float* conv2_b  = (const float*)d_in[5];
    const float* q_w      = (const float*)d_in[6];
    const float* q_b      = (const float*)d_in[7];
    const float* k_w      = (const float*)d_in[8];
    const float* k_b      = (const float*)d_in[9];
    const float* v_w      = (const float*)d_in[10];
    const float* v_b      = (const float*)d_in[11];
    const float* gamma    = (const float*)d_in[12];
    const float* bw       = (const float*)d_in[13];
    const float* bn_scale = (const float*)d_in[14];
    const float* bn_bias  = (const float*)d_in[15];
    float* out = (float*)d_out;

    __half *low16, *hf16, *qf16, *vf16, *vf216, *qb16, *kb16, *qt16, *kt16;
    __half *vb16, *vt16, *attH16, *attW16, *oh16, *ow16, *w16;
    float* statsp;
    cudaGetSymbolAddress((void**)&low16, g_low16);
    cudaGetSymbolAddress((void**)&hf16,  g_hf16);
    cudaGetSymbolAddress((void**)&qf16,  g_qf16);
    cudaGetSymbolAddress((void**)&vf16,  g_vf16);
    cudaGetSymbolAddress((void**)&vf216, g_vf216);
    cudaGetSymbolAddress((void**)&qb16,  g_qb16);
    cudaGetSymbolAddress((void**)&kb16,  g_kb16);
    cudaGetSymbolAddress((void**)&qt16,  g_qt16);
    cudaGetSymbolAddress((void**)&kt16,  g_kt16);
    cudaGetSymbolAddress((void**)&vb16,  g_vb16);
    cudaGetSymbolAddress((void**)&vt16,  g_vt16);
    cudaGetSymbolAddress((void**)&attH16, g_attH16);
    cudaGetSymbolAddress((void**)&attW16, g_attW16);
    cudaGetSymbolAddress((void**)&oh16,  g_oh16);
    cudaGetSymbolAddress((void**)&ow16,  g_ow16);
    cudaGetSymbolAddress((void**)&w16,   g_w16);
    cudaGetSymbolAddress((void**)&statsp, g_stats);

    cudaFuncSetAttribute(hgemm_kernel,   cudaFuncAttributeMaxDynamicSharedMemorySize, GEMMH_SMEM);
    cudaFuncSetAttribute(hgemm32_kernel, cudaFuncAttributeMaxDynamicSharedMemorySize, GEMMH32_SMEM);
    cudaFuncSetAttribute(pv_mma_kernel,  cudaFuncAttributeMaxDynamicSharedMemorySize, PV_SMEM);

    wcvt_kernel<<<720, 256>>>(conv1_w, conv2_w, v_w, k_w, q_w, bw, w16);
    resize_kernel<<<4096, 256>>>(high, hf16, low, low16, statsp);

    // conv1 -> qf16 ; conv2 -> vf16
    hgemm_kernel<<<dim3(72, 2, 8), 256, GEMMH_SMEM>>>(
        w16 + W_C1, 512, low16, 512LL * 9216, nullptr, 0, 1 << 30,
        conv1_b, qf16, 256LL * 9216, 512, 9216, nullptr);
    hgemm_kernel<<<dim3(72, 2, 8), 256, GEMMH_SMEM>>>(
        w16 + W_C2, 512, hf16, 512LL * 9216, nullptr, 0, 1 << 30,
        conv2_b, vf16, 256LL * 9216, 512, 9216, nullptr);
    hgemm32_kernel<<<dim3(36, 1, 8), 256, GEMMH32_SMEM>>>(
        w16 + W_Q, 256, qf16, 256LL * 9216, q_b, qb16, 32LL * 9216, 256, 9216);
    transpose16_kernel<<<dim3(3, 3, 256), dim3(32, 8)>>>(qb16, qt16, 256, qb16, qt16);

    for (int it = 0; it < 2; it++) {
        const __half* src = it ? vf216 : vf16;
        __half* dstp      = it ? vf16  : vf216;
        hgemm32_kernel<<<dim3(36, 1, 8), 256, GEMMH32_SMEM>>>(
            w16 + W_K, 256, src, 256LL * 9216, k_b, kb16, 32LL * 9216, 256, 9216);
        hgemm_kernel<<<dim3(72, 2, 8), 256, GEMMH_SMEM>>>(
            w16 + W_V, 256, src, 256LL * 9216, nullptr, 0, 1 << 30,
            v_b, vb16, 256LL * 9216, 256, 9216, nullptr);
        transpose16_kernel<<<dim3(3, 3, 2304), dim3(32, 8)>>>(kb16, kt16, 256, vb16, vt16);
        qk_kernel<<<dim3(96, 8, 2), 256>>>(qt16, kt16, qb16, kb16, attH16, attW16);
        softmax2_kernel<<<9216, dim3(32, 8)>>>(attH16, attW16);
        pv_mma_kernel<<<dim3(96, 8, 2), 256, PV_SMEM>>>(vt16, vb16, attH16, attW16, oh16, ow16);
        combine_kernel<<<dim3(3, 3, 2048), dim3(32, 8)>>>(ow16, oh16, src, gamma, dstp);
    }

    // bottleneck: K=768 fp16 -> fp16 scratch (low16, long dead) + fused BN stats
    hgemm_kernel<<<dim3(72, 4, 8), 256, GEMMH_SMEM>>>(
        w16 + W_BW, 768, vf16, 256LL * 9216, hf16, 512LL * 9216, 256,
        nullptr, low16, 512LL * 9216, 768, 9216, statsp);

    // batchnorm + relu: fp16 in -> fp32 out
    bn_apply_kernel<<<4608, 256>>>(low16, (float4*)out, statsp, bn_scale, bn_bias);
}